// round 9
// baseline (speedup 1.0000x reference)
#include <cuda_runtime.h>
#include <float.h>

#define NPTS 500
#define NP 8
#define NCOL 4000
#define NBLK 125
#define NB3  63    // blocks doing P2/P3 work (8 points each)

// ---------------- scratch (device globals) ----------------
__device__ int   g_inds[NCOL];
__device__ int   g_inds_tc[NCOL];
__device__ float g_expw[2 * NCOL];
__device__ float g_psum[1000];
__device__ float g_cf[NPTS * 128];
__device__ float g_imf[NPTS * 32];
__device__ float g_h1[NPTS * 64];
__device__ float g_hp[NPTS * 256];
__device__ float g_wps1T[128 * 256];
__device__ float g_wps2T[256 * 128];
__device__ float g_wc2T [64 * 128];
__device__ float g_wfc1T[256 * 64];
__device__ float g_wfc2T[160 * 64];
__device__ float g_wfcT [128 * 64];
__device__ int            g_ctr = 0;
__device__ volatile int   g_sense = 0;

__device__ __forceinline__ float lrelu(float x) { return x > 0.f ? x : 0.01f * x; }
__device__ __forceinline__ unsigned ordf(float f) {
    unsigned u = __float_as_uint(f);
    return (u & 0x80000000u) ? ~u : (u | 0x80000000u);
}
#define BARW(id) asm volatile("bar.sync %0, %1;" :: "r"(id), "r"(256) : "memory")

__device__ __forceinline__ void gbar(int phase) {
    __threadfence();
    __syncthreads();
    if (threadIdx.x == 0) {
        if (atomicAdd(&g_ctr, 1) == NBLK - 1) {
            g_ctr = 0;
            __threadfence();
            g_sense = phase;
        } else {
            while (g_sense != phase) __nanosleep(32);
            __threadfence();
        }
    }
    __syncthreads();
}

#define SMF 15440

__global__ __launch_bounds__(512) void uber(
        const float* __restrict__ c,   const float* __restrict__ ct,
        const float* __restrict__ imf,
        const float* __restrict__ wp1, const float* __restrict__ bp1,
        const float* __restrict__ wp2, const float* __restrict__ bp2,
        const float* __restrict__ wc1, const float* __restrict__ bc1,
        const float* __restrict__ wps1, const float* __restrict__ bps1,
        const float* __restrict__ wps2, const float* __restrict__ bps2,
        const float* __restrict__ wc2,  const float* __restrict__ bc2,
        const float* __restrict__ wfc1, const float* __restrict__ bfc1,
        const float* __restrict__ wfc2, const float* __restrict__ bfc2,
        const float* __restrict__ wfc,  const float* __restrict__ bfc,
        float* __restrict__ out) {
    extern __shared__ __align__(16) float sm[];
    int t = threadIdx.x;
    int b = blockIdx.x;

    // ========================= P1 (125 blocks: KNN + features + transposes) ====
    {
        int p0 = b * 4;
        if (t < 256) {
            // ---- KNN: 8 queries (warp/query), refs padded to 512 ----
            if (b <= 62) for (int i = t; i < 1536; i += 256) sm[i]        = (i < 1500) ? ct[i] : 1e18f;
            if (b >= 62) for (int i = t; i < 1536; i += 256) sm[1536 + i] = (i < 1500) ? c[i]  : 1e18f;
            BARW(1);

            int warp = t >> 5, lane = t & 31;
            int gw = b * 8 + warp;
            int dir = gw >= NPTS;
            int q = dir ? gw - NPTS : gw;
            const float* Qg = dir ? ct : c;
            float qx = __ldg(Qg + q * 3 + 0), qy = __ldg(Qg + q * 3 + 1), qz = __ldg(Qg + q * 3 + 2);
            float qq = qx * qx + qy * qy + qz * qz;

            const float* R = sm + (dir ? 1536 : 0);
            int j0 = lane * 16;
            float bd[8]; int bi[8];
#pragma unroll
            for (int k = 0; k < 8; k++) { bd[k] = FLT_MAX; bi[k] = 0x3fffffff; }

#pragma unroll
            for (int h8 = 0; h8 < 2; h8++) {
                float f[24];
                const float4* rp = (const float4*)(R + (j0 + h8 * 8) * 3);
#pragma unroll
                for (int v = 0; v < 6; v++) *(float4*)&f[v * 4] = rp[v];
#pragma unroll
                for (int jj = 0; jj < 8; jj++) {
                    float rx = f[jj * 3 + 0], ry = f[jj * 3 + 1], rz = f[jj * 3 + 2];
                    float d2 = qq - 2.f * (qx * rx + qy * ry + qz * rz) + (rx * rx + ry * ry + rz * rz);
                    int j = j0 + h8 * 8 + jj;
                    if (d2 < bd[7] || (d2 == bd[7] && j < bi[7])) {
                        bd[7] = d2; bi[7] = j;
#pragma unroll
                        for (int k = 7; k > 0; k--) {
                            if (bd[k] < bd[k - 1] || (bd[k] == bd[k - 1] && bi[k] < bi[k - 1])) {
                                float td = bd[k]; bd[k] = bd[k - 1]; bd[k - 1] = td;
                                int   ti = bi[k]; bi[k] = bi[k - 1]; bi[k - 1] = ti;
                            }
                        }
                    }
                }
            }

            int* selS = (int*)(sm + 3072);
#pragma unroll
            for (int s = 0; s < NP; s++) {
                unsigned key = ordf(bd[0]);
                unsigned mk  = __reduce_min_sync(0xffffffffu, key);
                unsigned mask = __ballot_sync(0xffffffffu, key == mk);
                int owner = __ffs(mask) - 1;
                if (lane == owner) {
                    selS[warp * 8 + s] = bi[0];
#pragma unroll
                    for (int k = 0; k < 7; k++) { bd[k] = bd[k + 1]; bi[k] = bi[k + 1]; }
                    bd[7] = FLT_MAX; bi[7] = 0x3fffffff;
                }
            }
            __syncwarp();

            int*   outi = dir ? g_inds_tc : g_inds;
            float* oute = dir ? (g_expw + NCOL) : g_expw;
            float e = 0.f;
            if (lane < NP) {
                int mi = selS[warp * 8 + lane];
                float dx = qx - R[mi * 3 + 0];
                float dy = qy - R[mi * 3 + 1];
                float dz = qz - R[mi * 3 + 2];
                e = expf(-sqrtf(dx * dx + dy * dy + dz * dz));
                outi[q * NP + lane] = mi;
                oute[q * NP + lane] = e;
            }
            if (lane < 8) {
                e += __shfl_xor_sync(0x000000ffu, e, 4);
                e += __shfl_xor_sync(0x000000ffu, e, 2);
                e += __shfl_xor_sync(0x000000ffu, e, 1);
                if (lane == 0) g_psum[gw] = e;
            }
        } else {
            // ---- features: 4 points + one transpose tile ----
            int t2 = t - 256;
            float* HS = sm + 3200;
            float* IS = sm + 3456;
            float* WC = sm + 3584;
            float* WT = sm + 5664;

            for (int e = t2; e < 2048; e += 256) {
                float4 v = __ldg((const float4*)(wp2 + e * 4));
                int r = e >> 4, k0 = (e & 15) * 4;
                WT[(k0 + 0) * 129 + r] = v.x;
                WT[(k0 + 1) * 129 + r] = v.y;
                WT[(k0 + 2) * 129 + r] = v.z;
                WT[(k0 + 3) * 129 + r] = v.w;
            }
            for (int e = t2; e < 512; e += 256) {
                float4 v = __ldg((const float4*)(wc1 + e * 4));
                int r = e >> 3, k0 = (e & 7) * 4;
                WC[(k0 + 0) * 65 + r] = v.x;
                WC[(k0 + 1) * 65 + r] = v.y;
                WC[(k0 + 2) * 65 + r] = v.z;
                WC[(k0 + 3) * 65 + r] = v.w;
            }
            if (t2 < 128) {
                int lp = t2 >> 5, chn = t2 & 31;
                float v = imf[chn * NPTS + (p0 + lp)];
                IS[lp * 32 + chn] = v;
                g_imf[(p0 + lp) * 32 + chn] = v;
            }
            {
                int lp = t2 >> 6, r = t2 & 63;
                int p = p0 + lp;
                float h = bp1[r] + wp1[r * 3 + 0] * c[p * 3 + 0] + wp1[r * 3 + 1] * c[p * 3 + 1]
                                 + wp1[r * 3 + 2] * c[p * 3 + 2];
                HS[lp * 64 + r] = lrelu(h);
            }
            BARW(2);

            {   // cf
                int r = t2 & 127, h = t2 >> 7;
                const float* x0 = HS + (2 * h) * 64;
                const float* x1 = HS + (2 * h + 1) * 64;
                float a0 = 0.f, a1 = 0.f;
#pragma unroll 8
                for (int k = 0; k < 64; k++) {
                    float w = WT[k * 129 + r];
                    a0 += w * x0[k];
                    a1 += w * x1[k];
                }
                float bb = __ldg(bp2 + r);
                g_cf[(p0 + 2 * h) * 128 + r]     = a0 + bb;
                g_cf[(p0 + 2 * h + 1) * 128 + r] = a1 + bb;
            }
            {   // h1
                int r = t2 & 63, cc = t2 >> 6;
                const float* xi = IS + cc * 32;
                float a = 0.f;
#pragma unroll 8
                for (int k = 0; k < 32; k++) a += WC[k * 65 + r] * xi[k];
                g_h1[(p0 + cc) * 64 + r] = lrelu(a + __ldg(bc1 + r));
            }

            if (b < 106) {
                const float* src; float* dst; int Rr, Cc, tile;
                if      (b < 32)  { src = wps2; dst = g_wps2T; Rr = 128; Cc = 256; tile = b; }
                else if (b < 40)  { src = wc2;  dst = g_wc2T;  Rr = 128; Cc = 64;  tile = b - 32; }
                else if (b < 56)  { src = wfc1; dst = g_wfc1T; Rr = 64;  Cc = 256; tile = b - 40; }
                else if (b < 66)  { src = wfc2; dst = g_wfc2T; Rr = 64;  Cc = 160; tile = b - 56; }
                else if (b < 74)  { src = wfc;  dst = g_wfcT;  Rr = 64;  Cc = 128; tile = b - 66; }
                else              { src = wps1; dst = g_wps1T; Rr = 256; Cc = 128; tile = b - 74; }
                int tilesC = Cc / 32;
                int tr = (tile / tilesC) * 32, tc = (tile % tilesC) * 32;
                float (*S)[33] = (float(*)[33])WT;
                int r = t2 >> 3, qd = t2 & 7;
                BARW(2);
                float4 v = *(const float4*)(src + (tr + r) * Cc + tc + qd * 4);
                S[r][qd * 4 + 0] = v.x; S[r][qd * 4 + 1] = v.y;
                S[r][qd * 4 + 2] = v.z; S[r][qd * 4 + 3] = v.w;
                BARW(2);
                float4 o;
                o.x = S[qd * 4 + 0][r]; o.y = S[qd * 4 + 1][r];
                o.z = S[qd * 4 + 2][r]; o.w = S[qd * 4 + 3][r];
                *(float4*)(dst + (tc + r) * Rr + tr + qd * 4) = o;
            }
        }
    }
    gbar(1);

    // ========================= P2 (63 blocks x 8 points): Hp + denominators ====
    if (b < NB3) {
        int p0 = b * 8;
        float* Xs  = sm;           // [8][128]
        float* P2P = sm + 1024;    // [32][256]
        float* RED = sm + 15360;   // [2][16] (spread over 64)
        {
            float v0 = (t < 500) ? g_psum[t]       : 0.f;
            float v1 = (t < 500) ? g_psum[500 + t] : 0.f;
#pragma unroll
            for (int off = 16; off; off >>= 1) {
                v0 += __shfl_xor_sync(0xffffffffu, v0, off);
                v1 += __shfl_xor_sync(0xffffffffu, v1, off);
            }
            if ((t & 31) == 0) { RED[t >> 5] = v0; RED[32 + (t >> 5)] = v1; }
        }
        if (t < 256) {
            int col = t >> 5, f = t & 31;
            int pp = min(p0 + col, NPTS - 1);
            *(float4*)&Xs[col * 128 + f * 4] = *(const float4*)&g_cf[pp * 128 + f * 4];
        }
        __syncthreads();
        if (t == 0) {
            float s0 = 0.f, s1 = 0.f;
#pragma unroll
            for (int w = 0; w < 16; w++) { s0 += RED[w]; s1 += RED[32 + w]; }
            sm[15424] = 1.f / s0;
            sm[15425] = 1.f / s1;
        }
        {   // Hp: 256 rows x 8 cols, K=128; rq=t&127 (rows rq*2), ks=t>>7 (4 x K=32)
            int rq = t & 127, ks = t >> 7;
            float2 a[8] = {};
            const float* wp = g_wps1T + (ks * 32) * 256 + rq * 2;
#pragma unroll
            for (int kg = 0; kg < 8; kg++) {
                float xk[8][4];
#pragma unroll
                for (int cc = 0; cc < 8; cc++)
                    *(float4*)xk[cc] = *(float4*)&Xs[cc * 128 + ks * 32 + kg * 4];
#pragma unroll
                for (int j = 0; j < 4; j++) {
                    float2 w2 = *(const float2*)(wp + (kg * 4 + j) * 256);
#pragma unroll
                    for (int cc = 0; cc < 8; cc++) {
                        a[cc].x += w2.x * xk[cc][j];
                        a[cc].y += w2.y * xk[cc][j];
                    }
                }
            }
#pragma unroll
            for (int cc = 0; cc < 8; cc++)
                *(float2*)&P2P[(ks * 8 + cc) * 256 + rq * 2] = a[cc];
        }
        __syncthreads();
        for (int o = t; o < 2048; o += 512) {
            int r = o & 255, cc = o >> 8;
            float s = 0.f;
#pragma unroll
            for (int ks = 0; ks < 4; ks++) s += P2P[(ks * 8 + cc) * 256 + r];
            int p = p0 + cc;
            if (p < NPTS) g_hp[p * 256 + r] = lrelu(s + bps1[r]);
        }
    }
    gbar(0);
    if (b >= NB3) return;

    // ========================= P3 (63 blocks x 8 points) =========================
    {
        int p0 = b * 8;
        int*   I0  = (int*)(sm + 0);       // 64
        int*   I1  = (int*)(sm + 64);
        float* W0  = sm + 128;
        float* W1  = sm + 192;
        float* Ws0 = sm + 256;
        float* Ws1 = sm + 264;
        float* Hb  = sm + 272;    // [8][64]
        float* Hpb = sm + 784;    // [8][256]
        float* A1  = sm + 2832;   // [8][256]  low=Sf high=Cf
        float* A2  = sm + 4880;   // [8][160]  low=Sfp high=Im
        float* Z   = sm + 6160;   // [8][128]
        float* PA  = sm + 7184;   // 4096
        float* PB  = sm + 11280;  // 4096
        float inv0 = sm[15424], inv1 = sm[15425];

        int wg = t >> 8, ta = t & 255;

        if (wg == 0) {
            if (ta < 64) {
                int e = min(p0 * NP + ta, NCOL - 1);
                I0[ta] = g_inds[e];    W0[ta] = g_expw[e];
                I1[ta] = g_inds_tc[e]; W1[ta] = g_expw[NCOL + e];
            } else if (ta < 128) {
                int tt = ta - 64;
                int col = tt >> 3, f = tt & 7;
                int pp = min(p0 + col, NPTS - 1);
                *(float4*)&A2[col * 160 + 128 + f * 4] = *(const float4*)&g_imf[pp * 32 + f * 4];
            }
        } else {
            int col = ta >> 5, f = ta & 31;
            int pp = min(p0 + col, NPTS - 1);
            *(float4*)&A1[col * 256 + 128 + f * 4] = *(const float4*)&g_cf[pp * 128 + f * 4];
        }
        __syncthreads();

        if (wg == 0) {
            // ========== chain A: Hpbar -> Y2 -> f2 -> Z low ==========
            if (ta < 8) {
                float s = 0;
#pragma unroll
                for (int j = 0; j < 8; j++) s += W1[ta * 8 + j];
                Ws1[ta] = 0.125f * inv1 * s;
            }
            {   // Hpbar[8][256]: r = ta
                int r = ta;
#pragma unroll
                for (int lp = 0; lp < 8; lp++) {
                    float s = 0;
#pragma unroll
                    for (int j = 0; j < 8; j++) s += W1[lp * 8 + j] * g_hp[I1[lp * 8 + j] * 256 + r];
                    Hpb[lp * 256 + r] = 0.125f * inv1 * s;
                }
            }
            BARW(1);
            {   // Y2: 128 rows x 8 cols, K=256; rq=ta&63 (rows rq*2), ks=ta>>6 (4 x K=64)
                int rq = ta & 63, ks = ta >> 6;
                float2 a[8] = {};
                const float* wp = g_wps2T + (ks * 64) * 128 + rq * 2;
#pragma unroll
                for (int kg = 0; kg < 16; kg++) {
                    float xk[8][4];
#pragma unroll
                    for (int cc = 0; cc < 8; cc++)
                        *(float4*)xk[cc] = *(float4*)&Hpb[cc * 256 + ks * 64 + kg * 4];
#pragma unroll
                    for (int j = 0; j < 4; j++) {
                        float2 w2 = *(const float2*)(wp + (kg * 4 + j) * 128);
#pragma unroll
                        for (int cc = 0; cc < 8; cc++) {
                            a[cc].x += w2.x * xk[cc][j];
                            a[cc].y += w2.y * xk[cc][j];
                        }
                    }
                }
#pragma unroll
                for (int cc = 0; cc < 8; cc++)
                    *(float2*)&PA[(ks * 8 + cc) * 128 + rq * 2] = a[cc];
            }
            BARW(1);
            for (int o = ta; o < 1024; o += 256) {   // -> Sfp (A2 low)
                int r = o & 127, cc = o >> 7;
                float s = 0;
#pragma unroll
                for (int ks = 0; ks < 4; ks++) s += PA[(ks * 8 + cc) * 128 + r];
                A2[cc * 160 + r] = s + bps2[r] * Ws1[cc];
            }
            BARW(1);
            {   // f2: 64 rows x 8 cols, K=160; rq=ta&31 (rows rq*2), ks=ta>>5 (8 x K=20)
                int rq = ta & 31, ks = ta >> 5;
                float2 a[8] = {};
                const float* wp = g_wfc2T + (ks * 20) * 64 + rq * 2;
#pragma unroll
                for (int kg = 0; kg < 5; kg++) {
                    float xk[8][4];
#pragma unroll
                    for (int cc = 0; cc < 8; cc++)
                        *(float4*)xk[cc] = *(float4*)&A2[cc * 160 + ks * 20 + kg * 4];
#pragma unroll
                    for (int j = 0; j < 4; j++) {
                        float2 w2 = *(const float2*)(wp + (kg * 4 + j) * 64);
#pragma unroll
                        for (int cc = 0; cc < 8; cc++) {
                            a[cc].x += w2.x * xk[cc][j];
                            a[cc].y += w2.y * xk[cc][j];
                        }
                    }
                }
#pragma unroll
                for (int cc = 0; cc < 8; cc++)
                    *(float2*)&PA[(ks * 8 + cc) * 64 + rq * 2] = a[cc];
            }
            BARW(1);
            for (int o = ta; o < 512; o += 256) {   // -> Z[:,ch] (f2 first)
                int ch = o & 63, cc = o >> 6;
                float s = 0;
#pragma unroll
                for (int ks = 0; ks < 8; ks++) s += PA[(ks * 8 + cc) * 64 + ch];
                Z[cc * 128 + ch] = lrelu(s + bfc2[ch]);
            }
        } else {
            // ========== chain B: Hbar -> Y1 -> f1 -> Z high ==========
            if (ta < 8) {
                float s = 0;
#pragma unroll
                for (int j = 0; j < 8; j++) s += W0[ta * 8 + j];
                Ws0[ta] = 0.125f * inv0 * s;
            }
            {   // Hbar[8][64]: r=ta&63, lps {lp2, lp2+4}
                int r = ta & 63, lp2 = ta >> 6;
#pragma unroll
                for (int q2 = 0; q2 < 2; q2++) {
                    int lp = lp2 + q2 * 4;
                    float s = 0;
#pragma unroll
                    for (int j = 0; j < 8; j++) s += W0[lp * 8 + j] * g_h1[I0[lp * 8 + j] * 64 + r];
                    Hb[lp * 64 + r] = 0.125f * inv0 * s;
                }
            }
            BARW(2);
            {   // Y1: 128 rows x 8 cols, K=64; rq=ta&63 (rows rq*2), ks=ta>>6 (4 x K=16)
                int rq = ta & 63, ks = ta >> 6;
                float2 a[8] = {};
                const float* wp = g_wc2T + (ks * 16) * 128 + rq * 2;
#pragma unroll
                for (int kg = 0; kg < 4; kg++) {
                    float xk[8][4];
#pragma unroll
                    for (int cc = 0; cc < 8; cc++)
                        *(float4*)xk[cc] = *(float4*)&Hb[cc * 64 + ks * 16 + kg * 4];
#pragma unroll
                    for (int j = 0; j < 4; j++) {
                        float2 w2 = *(const float2*)(wp + (kg * 4 + j) * 128);
#pragma unroll
                        for (int cc = 0; cc < 8; cc++) {
                            a[cc].x += w2.x * xk[cc][j];
                            a[cc].y += w2.y * xk[cc][j];
                        }
                    }
                }
#pragma unroll
                for (int cc = 0; cc < 8; cc++)
                    *(float2*)&PB[(ks * 8 + cc) * 128 + rq * 2] = a[cc];
            }
            BARW(2);
            for (int o = ta; o < 1024; o += 256) {   // -> Sf (A1 low)
                int r = o & 127, cc = o >> 7;
                float s = 0;
#pragma unroll
                for (int ks = 0; ks < 4; ks++) s += PB[(ks * 8 + cc) * 128 + r];
                A1[cc * 256 + r] = s + bc2[r] * Ws0[cc];
            }
            BARW(2);
            {   // f1: 64 rows x 8 cols, K=256; rq=ta&31 (rows rq*2), ks=ta>>5 (8 x K=32)
                int rq = ta & 31, ks = ta >> 5;
                float2 a[8] = {};
                const float* wp = g_wfc1T + (ks * 32) * 64 + rq * 2;
#pragma unroll
                for (int kg = 0; kg < 8; kg++) {
                    float xk[8][4];
#pragma unroll
                    for (int cc = 0; cc < 8; cc++)
                        *(float4*)xk[cc] = *(float4*)&A1[cc * 256 + ks * 32 + kg * 4];
#pragma unroll
                    for (int j = 0; j < 4; j++) {
                        float2 w2 = *(const float2*)(wp + (kg * 4 + j) * 64);
#pragma unroll
                        for (int cc = 0; cc < 8; cc++) {
                            a[cc].x += w2.x * xk[cc][j];
                            a[cc].y += w2.y * xk[cc][j];
                        }
                    }
                }
#pragma unroll
                for (int cc = 0; cc < 8; cc++)
                    *(float2*)&PB[(ks * 8 + cc) * 64 + rq * 2] = a[cc];
            }
            BARW(2);
            for (int o = ta; o < 512; o += 256) {   // -> Z[:,64+ch]
                int ch = o & 63, cc = o >> 6;
                float s = 0;
#pragma unroll
                for (int ks = 0; ks < 8; ks++) s += PB[(ks * 8 + cc) * 64 + ch];
                Z[cc * 128 + 64 + ch] = lrelu(s + bfc1[ch]);
            }
        }
        __syncthreads();

        {   // out: 64 rows x 8 cols, K=128; all 512 threads: rq=t&63 (1 row), ks=t>>6 (8 x K=16)
            int rq = t & 63, ks = t >> 6;
            float a[8] = {};
            const float* wp = g_wfcT + (ks * 16) * 64 + rq;
#pragma unroll
            for (int kg = 0; kg < 4; kg++) {
                float xk[8][4];
#pragma unroll
                for (int cc = 0; cc < 8; cc++)
                    *(float4*)xk[cc] = *(float4*)&Z[cc * 128 + ks * 16 + kg * 4];
#pragma unroll
                for (int j = 0; j < 4; j++) {
                    float w = wp[(kg * 4 + j) * 64];
#pragma unroll
                    for (int cc = 0; cc < 8; cc++) a[cc] += w * xk[cc][j];
                }
            }
#pragma unroll
            for (int cc = 0; cc < 8; cc++)
                PA[(ks * 8 + cc) * 64 + rq] = a[cc];
        }
        __syncthreads();
        {
            int ch = t & 63, cc = t >> 6;
            float s = 0;
#pragma unroll
            for (int ks = 0; ks < 8; ks++) s += PA[(ks * 8 + cc) * 64 + ch];
            int p = p0 + cc;
            if (p < NPTS) out[ch * NPTS + p] = s + bfc[ch];
        }
    }
}

// ---------------- launch ----------------
extern "C" void kernel_launch(void* const* d_in, const int* in_sizes, int n_in,
                              void* d_out, int out_size) {
    const float* imf   = (const float*)d_in[0];
    const float* cloud = (const float*)d_in[1];
    const float* ctar  = (const float*)d_in[2];
    const float* w_conv1   = (const float*)d_in[3];
    const float* b_conv1   = (const float*)d_in[4];
    const float* w_conv2   = (const float*)d_in[5];
    const float* b_conv2   = (const float*)d_in[6];
    const float* w_psconv1 = (const float*)d_in[7];
    const float* b_psconv1 = (const float*)d_in[8];
    const float* w_psconv2 = (const float*)d_in[9];
    const float* b_psconv2 = (const float*)d_in[10];
    const float* w_pconv1  = (const float*)d_in[11];
    const float* b_pconv1  = (const float*)d_in[12];
    const float* w_pconv2  = (const float*)d_in[13];
    const float* b_pconv2  = (const float*)d_in[14];
    const float* w_fc1 = (const float*)d_in[15];
    const float* b_fc1 = (const float*)d_in[16];
    const float* w_fc2 = (const float*)d_in[17];
    const float* b_fc2 = (const float*)d_in[18];
    const float* w_fc  = (const float*)d_in[19];
    const float* b_fc  = (const float*)d_in[20];
    float* out = (float*)d_out;

    static bool attr_set = false;
    if (!attr_set) {
        cudaFuncSetAttribute(uber, cudaFuncAttributeMaxDynamicSharedMemorySize, SMF * 4);
        attr_set = true;
    }
    uber<<<NBLK, 512, SMF * 4>>>(cloud, ctar, imf,
                                 w_pconv1, b_pconv1, w_pconv2, b_pconv2,
                                 w_conv1, b_conv1,
                                 w_psconv1, b_psconv1,
                                 w_psconv2, b_psconv2,
                                 w_conv2, b_conv2,
                                 w_fc1, b_fc1, w_fc2, b_fc2, w_fc, b_fc,
                                 out);
}

// round 10
// speedup vs baseline: 1.1485x; 1.1485x over previous
#include <cuda_runtime.h>
#include <float.h>

#define NPTS 500
#define NP 8
#define NCOL 4000
#define NBLK 125

// ---------------- scratch (device globals) ----------------
__device__ int   g_inds[NCOL];
__device__ int   g_inds_tc[NCOL];
__device__ float g_expw[2 * NCOL];
__device__ float g_psum[1000];
__device__ float g_cf[NPTS * 128];
__device__ float g_imf[NPTS * 32];
__device__ float g_h1[NPTS * 64];
__device__ float g_hp[NPTS * 256];
__device__ float g_wps1T[128 * 256];
__device__ float g_wps2T[256 * 128];
__device__ float g_wc2T [64 * 128];
__device__ float g_wfc1T[256 * 64];
__device__ float g_wfc2T[160 * 64];
__device__ float g_wfcT [128 * 64];
__device__ int            g_ctr = 0;
__device__ volatile int   g_sense = 0;

__device__ __forceinline__ float lrelu(float x) { return x > 0.f ? x : 0.01f * x; }
__device__ __forceinline__ unsigned ordf(float f) {
    unsigned u = __float_as_uint(f);
    return (u & 0x80000000u) ? ~u : (u | 0x80000000u);
}
#define BARW(id) asm volatile("bar.sync %0, %1;" :: "r"(id), "r"(256) : "memory")

__device__ __forceinline__ void gbar(int phase) {
    __threadfence();
    __syncthreads();
    if (threadIdx.x == 0) {
        if (atomicAdd(&g_ctr, 1) == NBLK - 1) {
            g_ctr = 0;
            __threadfence();
            g_sense = phase;
        } else {
            while (g_sense != phase) __nanosleep(32);
            __threadfence();
        }
    }
    __syncthreads();
}

#define SMF 15440

__global__ __launch_bounds__(512) void uber(
        const float* __restrict__ c,   const float* __restrict__ ct,
        const float* __restrict__ imf,
        const float* __restrict__ wp1, const float* __restrict__ bp1,
        const float* __restrict__ wp2, const float* __restrict__ bp2,
        const float* __restrict__ wc1, const float* __restrict__ bc1,
        const float* __restrict__ wps1, const float* __restrict__ bps1,
        const float* __restrict__ wps2, const float* __restrict__ bps2,
        const float* __restrict__ wc2,  const float* __restrict__ bc2,
        const float* __restrict__ wfc1, const float* __restrict__ bfc1,
        const float* __restrict__ wfc2, const float* __restrict__ bfc2,
        const float* __restrict__ wfc,  const float* __restrict__ bfc,
        float* __restrict__ out) {
    extern __shared__ __align__(16) float sm[];
    int t = threadIdx.x;
    int b = blockIdx.x;
    int p0 = b * 4;

    // ========================= P1 =========================
    if (t < 256) {
        // ---- KNN: 8 queries (warp/query), refs padded to 512 ----
        if (b <= 62) for (int i = t; i < 1536; i += 256) sm[i]        = (i < 1500) ? ct[i] : 1e18f;
        if (b >= 62) for (int i = t; i < 1536; i += 256) sm[1536 + i] = (i < 1500) ? c[i]  : 1e18f;
        BARW(1);

        int warp = t >> 5, lane = t & 31;
        int gw = b * 8 + warp;
        int dir = gw >= NPTS;
        int q = dir ? gw - NPTS : gw;
        const float* Qg = dir ? ct : c;
        float qx = __ldg(Qg + q * 3 + 0), qy = __ldg(Qg + q * 3 + 1), qz = __ldg(Qg + q * 3 + 2);
        float qq = qx * qx + qy * qy + qz * qz;

        const float* R = sm + (dir ? 1536 : 0);
        int j0 = lane * 16;
        float bd[8]; int bi[8];
#pragma unroll
        for (int k = 0; k < 8; k++) { bd[k] = FLT_MAX; bi[k] = 0x3fffffff; }

#pragma unroll
        for (int h8 = 0; h8 < 2; h8++) {
            float f[24];
            const float4* rp = (const float4*)(R + (j0 + h8 * 8) * 3);
#pragma unroll
            for (int v = 0; v < 6; v++) *(float4*)&f[v * 4] = rp[v];
#pragma unroll
            for (int jj = 0; jj < 8; jj++) {
                float rx = f[jj * 3 + 0], ry = f[jj * 3 + 1], rz = f[jj * 3 + 2];
                float d2 = qq - 2.f * (qx * rx + qy * ry + qz * rz) + (rx * rx + ry * ry + rz * rz);
                int j = j0 + h8 * 8 + jj;
                if (d2 < bd[7] || (d2 == bd[7] && j < bi[7])) {
                    bd[7] = d2; bi[7] = j;
#pragma unroll
                    for (int k = 7; k > 0; k--) {
                        if (bd[k] < bd[k - 1] || (bd[k] == bd[k - 1] && bi[k] < bi[k - 1])) {
                            float td = bd[k]; bd[k] = bd[k - 1]; bd[k - 1] = td;
                            int   ti = bi[k]; bi[k] = bi[k - 1]; bi[k - 1] = ti;
                        }
                    }
                }
            }
        }

        int* selS = (int*)(sm + 3072);
#pragma unroll
        for (int s = 0; s < NP; s++) {
            unsigned key = ordf(bd[0]);
            unsigned mk  = __reduce_min_sync(0xffffffffu, key);
            unsigned mask = __ballot_sync(0xffffffffu, key == mk);
            int owner = __ffs(mask) - 1;
            if (lane == owner) {
                selS[warp * 8 + s] = bi[0];
#pragma unroll
                for (int k = 0; k < 7; k++) { bd[k] = bd[k + 1]; bi[k] = bi[k + 1]; }
                bd[7] = FLT_MAX; bi[7] = 0x3fffffff;
            }
        }
        __syncwarp();

        int*   outi = dir ? g_inds_tc : g_inds;
        float* oute = dir ? (g_expw + NCOL) : g_expw;
        float e = 0.f;
        if (lane < NP) {
            int mi = selS[warp * 8 + lane];
            float dx = qx - R[mi * 3 + 0];
            float dy = qy - R[mi * 3 + 1];
            float dz = qz - R[mi * 3 + 2];
            e = expf(-sqrtf(dx * dx + dy * dy + dz * dz));
            outi[q * NP + lane] = mi;
            oute[q * NP + lane] = e;
        }
        if (lane < 8) {
            e += __shfl_xor_sync(0x000000ffu, e, 4);
            e += __shfl_xor_sync(0x000000ffu, e, 2);
            e += __shfl_xor_sync(0x000000ffu, e, 1);
            if (lane == 0) g_psum[gw] = e;
        }
    } else {
        // ---- features: 4 points (imf^T, H64, cf, h1) + one transpose tile ----
        int t2 = t - 256;
        float* HS = sm + 3200;           // [4][64]
        float* IS = sm + 3456;           // [4][32]
        float* WC = sm + 3584;           // [32][68]  wc1^T padded (16B rows)
        float* WT = sm + 5760;           // [64][132] wp2^T padded (16B rows)

        for (int e = t2; e < 2048; e += 256) {        // wp2 -> WT[k][r]
            float4 v = __ldg((const float4*)(wp2 + e * 4));
            int r = e >> 4, k0 = (e & 15) * 4;
            WT[(k0 + 0) * 132 + r] = v.x;
            WT[(k0 + 1) * 132 + r] = v.y;
            WT[(k0 + 2) * 132 + r] = v.z;
            WT[(k0 + 3) * 132 + r] = v.w;
        }
        for (int e = t2; e < 512; e += 256) {         // wc1 -> WC[k][r]
            float4 v = __ldg((const float4*)(wc1 + e * 4));
            int r = e >> 3, k0 = (e & 7) * 4;
            WC[(k0 + 0) * 68 + r] = v.x;
            WC[(k0 + 1) * 68 + r] = v.y;
            WC[(k0 + 2) * 68 + r] = v.z;
            WC[(k0 + 3) * 68 + r] = v.w;
        }
        if (t2 < 128) {
            int lp = t2 >> 5, chn = t2 & 31;
            float v = imf[chn * NPTS + (p0 + lp)];
            IS[lp * 32 + chn] = v;
            g_imf[(p0 + lp) * 32 + chn] = v;
        }
        {
            int lp = t2 >> 6, r = t2 & 63;
            int p = p0 + lp;
            float h = bp1[r] + wp1[r * 3 + 0] * c[p * 3 + 0] + wp1[r * 3 + 1] * c[p * 3 + 1]
                             + wp1[r * 3 + 2] * c[p * 3 + 2];
            HS[lp * 64 + r] = lrelu(h);
        }
        BARW(2);

        if (t2 < 128) {   // cf: thread = (rowquad rq, point pt); LDS.128 w + broadcast x
            int rq = t2 & 31, pt = t2 >> 5;
            const float* x = HS + pt * 64;
            float4 a = {0.f, 0.f, 0.f, 0.f};
#pragma unroll 8
            for (int k = 0; k < 64; k++) {
                float4 w = *(float4*)&WT[k * 132 + rq * 4];
                float xv = x[k];
                a.x += w.x * xv; a.y += w.y * xv; a.z += w.z * xv; a.w += w.w * xv;
            }
            float4 bb = __ldg((const float4*)(bp2 + rq * 4));
            a.x += bb.x; a.y += bb.y; a.z += bb.z; a.w += bb.w;
            *(float4*)&g_cf[(p0 + pt) * 128 + rq * 4] = a;
        } else if (t2 < 192) {  // h1
            int u = t2 - 128, rq = u & 15, pt = u >> 4;
            const float* xi = IS + pt * 32;
            float4 a = {0.f, 0.f, 0.f, 0.f};
#pragma unroll 8
            for (int k = 0; k < 32; k++) {
                float4 w = *(float4*)&WC[k * 68 + rq * 4];
                float xv = xi[k];
                a.x += w.x * xv; a.y += w.y * xv; a.z += w.z * xv; a.w += w.w * xv;
            }
            float4 bb = __ldg((const float4*)(bc1 + rq * 4));
            float4 o;
            o.x = lrelu(a.x + bb.x); o.y = lrelu(a.y + bb.y);
            o.z = lrelu(a.z + bb.z); o.w = lrelu(a.w + bb.w);
            *(float4*)&g_h1[(p0 + pt) * 64 + rq * 4] = o;
        }

        if (b < 106) {   // one 32x32 transpose tile per block
            const float* src; float* dst; int Rr, Cc, tile;
            if      (b < 32)  { src = wps2; dst = g_wps2T; Rr = 128; Cc = 256; tile = b; }
            else if (b < 40)  { src = wc2;  dst = g_wc2T;  Rr = 128; Cc = 64;  tile = b - 32; }
            else if (b < 56)  { src = wfc1; dst = g_wfc1T; Rr = 64;  Cc = 256; tile = b - 40; }
            else if (b < 66)  { src = wfc2; dst = g_wfc2T; Rr = 64;  Cc = 160; tile = b - 56; }
            else if (b < 74)  { src = wfc;  dst = g_wfcT;  Rr = 64;  Cc = 128; tile = b - 66; }
            else              { src = wps1; dst = g_wps1T; Rr = 256; Cc = 128; tile = b - 74; }
            int tilesC = Cc / 32;
            int tr = (tile / tilesC) * 32, tc = (tile % tilesC) * 32;
            float (*S)[33] = (float(*)[33])WT;   // alias (WT dead after cf)
            int r = t2 >> 3, qd = t2 & 7;
            BARW(2);
            float4 v = *(const float4*)(src + (tr + r) * Cc + tc + qd * 4);
            S[r][qd * 4 + 0] = v.x; S[r][qd * 4 + 1] = v.y;
            S[r][qd * 4 + 2] = v.z; S[r][qd * 4 + 3] = v.w;
            BARW(2);
            float4 o;
            o.x = S[qd * 4 + 0][r]; o.y = S[qd * 4 + 1][r];
            o.z = S[qd * 4 + 2][r]; o.w = S[qd * 4 + 3][r];
            *(float4*)(dst + (tc + r) * Rr + tr + qd * 4) = o;
        }
    }
    gbar(1);

    // ========================= P2: Hp + denominators =========================
    {
        float* Xs  = sm;          // [4][128]
        float* P2P = sm + 512;    // [32][256]
        float* RED = sm + 12900;
        {
            float v0 = (t < 500) ? g_psum[t]       : 0.f;
            float v1 = (t < 500) ? g_psum[500 + t] : 0.f;
#pragma unroll
            for (int off = 16; off; off >>= 1) {
                v0 += __shfl_xor_sync(0xffffffffu, v0, off);
                v1 += __shfl_xor_sync(0xffffffffu, v1, off);
            }
            if ((t & 31) == 0) { RED[t >> 5] = v0; RED[32 + (t >> 5)] = v1; }
        }
        if (t < 128) {
            int col = t >> 5, f = t & 31;
            *(float4*)&Xs[col * 128 + f * 4] = *(const float4*)&g_cf[(p0 + col) * 128 + f * 4];
        }
        __syncthreads();
        if (t == 0) {
            float s0 = 0.f, s1 = 0.f;
#pragma unroll
            for (int w = 0; w < 16; w++) { s0 += RED[w]; s1 += RED[32 + w]; }
            sm[13000] = 1.f / s0;
            sm[13001] = 1.f / s1;
        }
        {   // Hp: 256 rows x 4 cols, K=128; rq=t&63, ks=t>>6 (8 x K=16)
            int rq = t & 63, ks = t >> 6;
            float4 a[4] = {};
            const float* wp = g_wps1T + (ks * 16) * 256 + rq * 4;
#pragma unroll
            for (int kg = 0; kg < 4; kg++) {
                float xk[4][4];
#pragma unroll
                for (int cc = 0; cc < 4; cc++)
                    *(float4*)xk[cc] = *(float4*)&Xs[cc * 128 + ks * 16 + kg * 4];
#pragma unroll
                for (int j = 0; j < 4; j++) {
                    float4 w4 = *(const float4*)(wp + (kg * 4 + j) * 256);
#pragma unroll
                    for (int cc = 0; cc < 4; cc++) {
                        float x = xk[cc][j];
                        a[cc].x += w4.x * x; a[cc].y += w4.y * x; a[cc].z += w4.z * x; a[cc].w += w4.w * x;
                    }
                }
            }
#pragma unroll
            for (int cc = 0; cc < 4; cc++)
                *(float4*)&P2P[(ks * 4 + cc) * 256 + rq * 4] = a[cc];
        }
        __syncthreads();
        for (int o = t; o < 1024; o += 512) {
            int r = o & 255, cc = o >> 8;
            float s = 0.f;
#pragma unroll
            for (int ks = 0; ks < 8; ks++) s += P2P[(ks * 4 + cc) * 256 + r];
            g_hp[(p0 + cc) * 256 + r] = lrelu(s + bps1[r]);
        }
    }
    gbar(0);

    // ========================= P3: gathers + GEMM chain =========================
    {
        int*   I0  = (int*)(sm + 0);
        int*   I1  = (int*)(sm + 32);
        float* W0  = sm + 64;
        float* W1  = sm + 96;
        float* Ws0 = sm + 128;
        float* Ws1 = sm + 132;
        float* Hb  = sm + 136;    // [4][64]
        float* Hpb = sm + 392;    // [4][256]
        float* A1  = sm + 1416;   // [4][256]  low=Sf high=Cf
        float* A2  = sm + 2440;   // [4][160]  low=Sfp high=Im
        float* Z   = sm + 3080;   // [4][128]
        float* PA  = sm + 3592;   // 4096
        float* PB  = sm + 7688;   // 4096
        float inv0 = sm[13000], inv1 = sm[13001];

        int wg = t >> 8, ta = t & 255;

        if (wg == 0) {
            if (ta < 32) {
                int e = p0 * NP + ta;
                I0[ta] = g_inds[e];    W0[ta] = g_expw[e];
                I1[ta] = g_inds_tc[e]; W1[ta] = g_expw[NCOL + e];
            } else if (ta < 64) {
                int tt = ta - 32;
                int col = tt >> 3, f = tt & 7;
                *(float4*)&A2[col * 160 + 128 + f * 4] = *(const float4*)&g_imf[(p0 + col) * 32 + f * 4];
            }
        } else {
            if (ta < 128) {
                int col = ta >> 5, f = ta & 31;
                *(float4*)&A1[col * 256 + 128 + f * 4] = *(const float4*)&g_cf[(p0 + col) * 128 + f * 4];
            }
        }
        __syncthreads();

        if (wg == 0) {
            if (ta < 4) {
                float s = 0;
#pragma unroll
                for (int j = 0; j < 8; j++) s += W1[ta * 8 + j];
                Ws1[ta] = 0.125f * inv1 * s;
            }
            {
                int r = ta;
#pragma unroll
                for (int lp = 0; lp < 4; lp++) {
                    float s = 0;
#pragma unroll
                    for (int j = 0; j < 8; j++) s += W1[lp * 8 + j] * g_hp[I1[lp * 8 + j] * 256 + r];
                    Hpb[lp * 256 + r] = 0.125f * inv1 * s;
                }
            }
            BARW(1);
            {   // Y2: 128 rows, K=256
                int rq = ta & 31, ks = ta >> 5;
                float4 a[4] = {};
                const float* wp = g_wps2T + (ks * 32) * 128 + rq * 4;
#pragma unroll
                for (int kg = 0; kg < 8; kg++) {
                    float xk[4][4];
#pragma unroll
                    for (int cc = 0; cc < 4; cc++)
                        *(float4*)xk[cc] = *(float4*)&Hpb[cc * 256 + ks * 32 + kg * 4];
#pragma unroll
                    for (int j = 0; j < 4; j++) {
                        float4 w4 = *(const float4*)(wp + (kg * 4 + j) * 128);
#pragma unroll
                        for (int cc = 0; cc < 4; cc++) {
                            float x = xk[cc][j];
                            a[cc].x += w4.x * x; a[cc].y += w4.y * x; a[cc].z += w4.z * x; a[cc].w += w4.w * x;
                        }
                    }
                }
#pragma unroll
                for (int cc = 0; cc < 4; cc++)
                    *(float4*)&PA[(ks * 4 + cc) * 128 + rq * 4] = a[cc];
            }
            BARW(1);
            for (int o = ta; o < 512; o += 256) {
                int r = o & 127, cc = o >> 7;
                float s = 0;
#pragma unroll
                for (int ks = 0; ks < 8; ks++) s += PA[(ks * 4 + cc) * 128 + r];
                A2[cc * 160 + r] = s + bps2[r] * Ws1[cc];
            }
            BARW(1);
            {   // f2: 64 rows, K=160
                int rq = ta & 15, ks = ta >> 4;
                float4 a[4] = {};
                const float* wp = g_wfc2T + (ks * 10) * 64 + rq * 4;
#pragma unroll
                for (int k = 0; k < 10; k++) {
                    float4 w4 = *(const float4*)(wp + k * 64);
                    int kk = ks * 10 + k;
#pragma unroll
                    for (int cc = 0; cc < 4; cc++) {
                        float x = A2[cc * 160 + kk];
                        a[cc].x += w4.x * x; a[cc].y += w4.y * x; a[cc].z += w4.z * x; a[cc].w += w4.w * x;
                    }
                }
#pragma unroll
                for (int cc = 0; cc < 4; cc++)
                    *(float4*)&PA[(ks * 4 + cc) * 64 + rq * 4] = a[cc];
            }
            BARW(1);
            {
                int ch = ta & 63, cc = ta >> 6;
                float s = 0;
#pragma unroll
                for (int ks = 0; ks < 16; ks++) s += PA[(ks * 4 + cc) * 64 + ch];
                Z[cc * 128 + ch] = lrelu(s + bfc2[ch]);
            }
        } else {
            if (ta < 4) {
                float s = 0;
#pragma unroll
                for (int j = 0; j < 8; j++) s += W0[ta * 8 + j];
                Ws0[ta] = 0.125f * inv0 * s;
            }
            {
                int lp = ta >> 6, r = ta & 63;
                float s = 0;
#pragma unroll
                for (int j = 0; j < 8; j++) s += W0[lp * 8 + j] * g_h1[I0[lp * 8 + j] * 64 + r];
                Hb[lp * 64 + r] = 0.125f * inv0 * s;
            }
            BARW(2);
            {   // Y1: 128 rows, K=64
                int rq = ta & 31, ks = ta >> 5;
                float4 a[4] = {};
                const float* wp = g_wc2T + (ks * 8) * 128 + rq * 4;
#pragma unroll
                for (int kg = 0; kg < 2; kg++) {
                    float xk[4][4];
#pragma unroll
                    for (int cc = 0; cc < 4; cc++)
                        *(float4*)xk[cc] = *(float4*)&Hb[cc * 64 + ks * 8 + kg * 4];
#pragma unroll
                    for (int j = 0; j < 4; j++) {
                        float4 w4 = *(const float4*)(wp + (kg * 4 + j) * 128);
#pragma unroll
                        for (int cc = 0; cc < 4; cc++) {
                            float x = xk[cc][j];
                            a[cc].x += w4.x * x; a[cc].y += w4.y * x; a[cc].z += w4.z * x; a[cc].w += w4.w * x;
                        }
                    }
                }
#pragma unroll
                for (int cc = 0; cc < 4; cc++)
                    *(float4*)&PB[(ks * 4 + cc) * 128 + rq * 4] = a[cc];
            }
            BARW(2);
            for (int o = ta; o < 512; o += 256) {
                int r = o & 127, cc = o >> 7;
                float s = 0;
#pragma unroll
                for (int ks = 0; ks < 8; ks++) s += PB[(ks * 4 + cc) * 128 + r];
                A1[cc * 256 + r] = s + bc2[r] * Ws0[cc];
            }
            BARW(2);
            {   // f1: 64 rows, K=256
                int rq = ta & 15, ks = ta >> 4;
                float4 a[4] = {};
                const float* wp = g_wfc1T + (ks * 16) * 64 + rq * 4;
#pragma unroll
                for (int kg = 0; kg < 4; kg++) {
                    float xk[4][4];
#pragma unroll
                    for (int cc = 0; cc < 4; cc++)
                        *(float4*)xk[cc] = *(float4*)&A1[cc * 256 + ks * 16 + kg * 4];
#pragma unroll
                    for (int j = 0; j < 4; j++) {
                        float4 w4 = *(const float4*)(wp + (kg * 4 + j) * 64);
#pragma unroll
                        for (int cc = 0; cc < 4; cc++) {
                            float x = xk[cc][j];
                            a[cc].x += w4.x * x; a[cc].y += w4.y * x; a[cc].z += w4.z * x; a[cc].w += w4.w * x;
                        }
                    }
                }
#pragma unroll
                for (int cc = 0; cc < 4; cc++)
                    *(float4*)&PB[(ks * 4 + cc) * 64 + rq * 4] = a[cc];
            }
            BARW(2);
            {
                int ch = ta & 63, cc = ta >> 6;
                float s = 0;
#pragma unroll
                for (int ks = 0; ks < 16; ks++) s += PB[(ks * 4 + cc) * 64 + ch];
                Z[cc * 128 + 64 + ch] = lrelu(s + bfc1[ch]);
            }
        }
        __syncthreads();

        if (wg == 0) {
            {   // out: 64 rows, K=128
                int rq = ta & 15, ks = ta >> 4;
                float4 a[4] = {};
                const float* wp = g_wfcT + (ks * 8) * 64 + rq * 4;
#pragma unroll
                for (int kg = 0; kg < 2; kg++) {
                    float xk[4][4];
#pragma unroll
                    for (int cc = 0; cc < 4; cc++)
                        *(float4*)xk[cc] = *(float4*)&Z[cc * 128 + ks * 8 + kg * 4];
#pragma unroll
                    for (int j = 0; j < 4; j++) {
                        float4 w4 = *(const float4*)(wp + (kg * 4 + j) * 64);
#pragma unroll
                        for (int cc = 0; cc < 4; cc++) {
                            float x = xk[cc][j];
                            a[cc].x += w4.x * x; a[cc].y += w4.y * x; a[cc].z += w4.z * x; a[cc].w += w4.w * x;
                        }
                    }
                }
#pragma unroll
                for (int cc = 0; cc < 4; cc++)
                    *(float4*)&PA[(ks * 4 + cc) * 64 + rq * 4] = a[cc];
            }
            BARW(1);
            {
                int ch = ta & 63, cc = ta >> 6;
                float s = 0;
#pragma unroll
                for (int ks = 0; ks < 16; ks++) s += PA[(ks * 4 + cc) * 64 + ch];
                out[ch * NPTS + (p0 + cc)] = s + bfc[ch];
            }
        }
    }
}

// ---------------- launch ----------------
extern "C" void kernel_launch(void* const* d_in, const int* in_sizes, int n_in,
                              void* d_out, int out_size) {
    const float* imf   = (const float*)d_in[0];
    const float* cloud = (const float*)d_in[1];
    const float* ctar  = (const float*)d_in[2];
    const float* w_conv1   = (const float*)d_in[3];
    const float* b_conv1   = (const float*)d_in[4];
    const float* w_conv2   = (const float*)d_in[5];
    const float* b_conv2   = (const float*)d_in[6];
    const float* w_psconv1 = (const float*)d_in[7];
    const float* b_psconv1 = (const float*)d_in[8];
    const float* w_psconv2 = (const float*)d_in[9];
    const float* b_psconv2 = (const float*)d_in[10];
    const float* w_pconv1  = (const float*)d_in[11];
    const float* b_pconv1  = (const float*)d_in[12];
    const float* w_pconv2  = (const float*)d_in[13];
    const float* b_pconv2  = (const float*)d_in[14];
    const float* w_fc1 = (const float*)d_in[15];
    const float* b_fc1 = (const float*)d_in[16];
    const float* w_fc2 = (const float*)d_in[17];
    const float* b_fc2 = (const float*)d_in[18];
    const float* w_fc  = (const float*)d_in[19];
    const float* b_fc  = (const float*)d_in[20];
    float* out = (float*)d_out;

    static bool attr_set = false;
    if (!attr_set) {
        cudaFuncSetAttribute(uber, cudaFuncAttributeMaxDynamicSharedMemorySize, SMF * 4);
        attr_set = true;
    }
    uber<<<NBLK, 512, SMF * 4>>>(cloud, ctar, imf,
                                 w_pconv1, b_pconv1, w_pconv2, b_pconv2,
                                 w_conv1, b_conv1,
                                 w_psconv1, b_psconv1,
                                 w_psconv2, b_psconv2,
                                 w_conv2, b_conv2,
                                 w_fc1, b_fc1, w_fc2, b_fc2, w_fc, b_fc,
                                 out);
}